// round 11
// baseline (speedup 1.0000x reference)
#include <cuda_runtime.h>

// ---------------------------------------------------------------------------
// TransformerEncoder: B=2, S=2048, D=512, H=8, DH=64, F=2048, L=6, fp32
// ---------------------------------------------------------------------------

#define NLAYER 6
#define DMODEL 512
#define SEQ    2048
#define BATCH  2
#define NHEAD  8
#define DHEAD  64
#define FFDIM  2048
#define MTOK   (BATCH * SEQ)   // 4096 tokens

// Scratch (device globals; allocation is forbidden)
__device__ float g_h  [MTOK * DMODEL];        // residual stream
__device__ float g_y  [MTOK * DMODEL];        // layernorm output
__device__ float g_qkv[MTOK * 3 * DMODEL];    // QKV projection
__device__ float g_att[MTOK * DMODEL];        // attention output
__device__ float g_ffn[MTOK * FFDIM];         // FFN hidden

// ---------------------------------------------------------------------------
// LayerNorm: one block (128 threads) per token, D=512 (4 floats/thread)
// ---------------------------------------------------------------------------
__global__ void ln_kernel(const float* __restrict__ x,
                          const float* __restrict__ w,
                          const float* __restrict__ b,
                          float* __restrict__ y)
{
    const int token = blockIdx.x;
    const int t = threadIdx.x;
    const float4 v = ((const float4*)(x + (size_t)token * DMODEL))[t];
    float s  = v.x + v.y + v.z + v.w;
    float ss = v.x * v.x + v.y * v.y + v.z * v.z + v.w * v.w;
    #pragma unroll
    for (int o = 16; o > 0; o >>= 1) {
        s  += __shfl_xor_sync(0xffffffffu, s,  o);
        ss += __shfl_xor_sync(0xffffffffu, ss, o);
    }
    __shared__ float rs[4], rss[4];
    const int warp = t >> 5, lane = t & 31;
    if (lane == 0) { rs[warp] = s; rss[warp] = ss; }
    __syncthreads();
    s  = rs[0]  + rs[1]  + rs[2]  + rs[3];
    ss = rss[0] + rss[1] + rss[2] + rss[3];
    const float mean = s * (1.0f / DMODEL);
    const float var  = ss * (1.0f / DMODEL) - mean * mean;
    const float r    = rsqrtf(var + 1e-5f);
    const float4 wv = ((const float4*)w)[t];
    const float4 bv = ((const float4*)b)[t];
    float4 ov;
    ov.x = (v.x - mean) * r * wv.x + bv.x;
    ov.y = (v.y - mean) * r * wv.y + bv.y;
    ov.z = (v.z - mean) * r * wv.z + bv.z;
    ov.w = (v.w - mean) * r * wv.w + bv.w;
    ((float4*)(y + (size_t)token * DMODEL))[t] = ov;
}

// ---------------------------------------------------------------------------
// SGEMM: C[M,N] = A[M,K] @ B[K,N] + bias (+ residual) (optional ReLU)
// 128x128 block tile, BK=8, 8x8 per thread, 256 threads.
// M,N multiples of 128; K multiple of 8 (holds for all call sites).
// ---------------------------------------------------------------------------
template<bool RELU, bool RES>
__global__ __launch_bounds__(256)
void sgemm128(const int M, const int N, const int K,
              const float* __restrict__ A, const float* __restrict__ B,
              const float* __restrict__ bias, const float* __restrict__ res,
              float* __restrict__ C)
{
    __shared__ float As[8][128];   // transposed A tile
    __shared__ float Bs[8][128];
    const int tid  = threadIdx.x;
    const int row0 = blockIdx.y * 128;
    const int col0 = blockIdx.x * 128;
    const int aRow = tid >> 1, aCol = (tid & 1) * 4;
    const int bRow = tid >> 5, bCol = (tid & 31) * 4;
    const int ty = tid >> 4, tx = tid & 15;
    const float* Ag = A + (size_t)(row0 + aRow) * K + aCol;
    const float* Bg = B + (size_t)bRow * N + col0 + bCol;

    float acc[8][8] = {};
    for (int k0 = 0; k0 < K; k0 += 8) {
        const float4 a = *(const float4*)(Ag + k0);
        As[aCol + 0][aRow] = a.x;
        As[aCol + 1][aRow] = a.y;
        As[aCol + 2][aRow] = a.z;
        As[aCol + 3][aRow] = a.w;
        *(float4*)(&Bs[bRow][bCol]) = *(const float4*)(Bg + (size_t)k0 * N);
        __syncthreads();
        #pragma unroll
        for (int k = 0; k < 8; k++) {
            float ra[8], rb[8];
            *(float4*)(ra)     = *(const float4*)(&As[k][ty * 8]);
            *(float4*)(ra + 4) = *(const float4*)(&As[k][ty * 8 + 4]);
            *(float4*)(rb)     = *(const float4*)(&Bs[k][tx * 8]);
            *(float4*)(rb + 4) = *(const float4*)(&Bs[k][tx * 8 + 4]);
            #pragma unroll
            for (int i = 0; i < 8; i++)
                #pragma unroll
                for (int j = 0; j < 8; j++)
                    acc[i][j] += ra[i] * rb[j];
        }
        __syncthreads();
    }

    #pragma unroll
    for (int i = 0; i < 8; i++) {
        const size_t r = (size_t)(row0 + ty * 8 + i);
        #pragma unroll
        for (int j = 0; j < 8; j += 4) {
            const int c = col0 + tx * 8 + j;
            const float4 bv = *(const float4*)(bias + c);
            float4 v;
            v.x = acc[i][j + 0] + bv.x;
            v.y = acc[i][j + 1] + bv.y;
            v.z = acc[i][j + 2] + bv.z;
            v.w = acc[i][j + 3] + bv.w;
            if (RES) {
                const float4 rv = *(const float4*)(res + r * N + c);
                v.x += rv.x; v.y += rv.y; v.z += rv.z; v.w += rv.w;
            }
            if (RELU) {
                v.x = fmaxf(v.x, 0.f); v.y = fmaxf(v.y, 0.f);
                v.z = fmaxf(v.z, 0.f); v.w = fmaxf(v.w, 0.f);
            }
            *(float4*)(C + r * N + c) = v;
        }
    }
}

// ---------------------------------------------------------------------------
// Fused fp32 flash attention.
// grid (S/64, H, B), 256 threads. Each block: 64 queries x full K/V sweep
// with online softmax. Per thread: 4x4 micro-tile (16x16 thread grid).
// smem: Q[64][68] row-major, K^T[64][68], V[64][68], P[64][68], row stats.
// ---------------------------------------------------------------------------
#define APAD 68
#define ATT_SMEM_BYTES ((4 * 64 * APAD + 3 * 64) * (int)sizeof(float))

__global__ __launch_bounds__(256)
void attn_kernel(const float* __restrict__ qkv,
                 const float* __restrict__ mask,
                 float* __restrict__ out)
{
    extern __shared__ float sm[];
    float* Qs  = sm;                   // [64][APAD]  (scaled Q)
    float* KsT = Qs  + 64 * APAD;      // [d][col]
    float* Vs  = KsT + 64 * APAD;      // [k][col]
    float* Ps  = Vs  + 64 * APAD;      // [row][col]
    float* rm  = Ps  + 64 * APAD;      // running max [64]
    float* rl  = rm  + 64;             // running sum [64]
    float* rc  = rl  + 64;             // correction  [64]

    const int tid = threadIdx.x;
    const int qt = blockIdx.x, h = blockIdx.y, b = blockIdx.z;
    const int q0 = qt * 64;
    const int ty = tid >> 4, tx = tid & 15;
    const int lr = tid >> 2;            // load row   0..63
    const int lc = (tid & 3) * 16;      // load col group

    // Load Q tile, pre-scaled by DH^-0.5 = 0.125
    {
        const float* qsrc = qkv + (size_t)(b * SEQ + q0 + lr) * 1536 + h * 64 + lc;
        float* qdst = Qs + lr * APAD + lc;
        #pragma unroll
        for (int u = 0; u < 16; u += 4) {
            float4 v = *(const float4*)(qsrc + u);
            v.x *= 0.125f; v.y *= 0.125f; v.z *= 0.125f; v.w *= 0.125f;
            *(float4*)(qdst + u) = v;
        }
    }
    if (tid < 64) { rm[tid] = -1e30f; rl[tid] = 0.f; }

    float o[4][4] = {};

    for (int k0 = 0; k0 < SEQ; k0 += 64) {
        __syncthreads();   // previous PV done; Q/stats visible on first iter
        // Load K (transposed into smem) and V (natural)
        {
            const float* kb = qkv + (size_t)(b * SEQ + k0 + lr) * 1536 + 512 + h * 64 + lc;
            #pragma unroll
            for (int u = 0; u < 16; u += 4) {
                const float4 v = *(const float4*)(kb + u);
                KsT[(lc + u + 0) * APAD + lr] = v.x;
                KsT[(lc + u + 1) * APAD + lr] = v.y;
                KsT[(lc + u + 2) * APAD + lr] = v.z;
                KsT[(lc + u + 3) * APAD + lr] = v.w;
            }
            const float* vb = qkv + (size_t)(b * SEQ + k0 + lr) * 1536 + 1024 + h * 64 + lc;
            float* vd = Vs + lr * APAD + lc;
            #pragma unroll
            for (int u = 0; u < 16; u += 4)
                *(float4*)(vd + u) = *(const float4*)(vb + u);
        }
        __syncthreads();

        // Scores: s[i][j] = sum_d Q[4ty+i][d] * K[4tx+j][d]
        float s[4][4] = {};
        #pragma unroll
        for (int d = 0; d < 64; d += 4) {
            float4 qv[4], kv[4];
            #pragma unroll
            for (int i = 0; i < 4; i++)
                qv[i] = *(const float4*)(Qs + (ty * 4 + i) * APAD + d);
            #pragma unroll
            for (int dd = 0; dd < 4; dd++)
                kv[dd] = *(const float4*)(KsT + (d + dd) * APAD + tx * 4);
            const float* qf = (const float*)qv;
            const float* kf = (const float*)kv;
            #pragma unroll
            for (int dd = 0; dd < 4; dd++)
                #pragma unroll
                for (int i = 0; i < 4; i++)
                    #pragma unroll
                    for (int j = 0; j < 4; j++)
                        s[i][j] += qf[i * 4 + dd] * kf[dd * 4 + j];
        }

        // Add mask, write scores to smem
        {
            const float4 mv = *(const float4*)(mask + b * SEQ + k0 + tx * 4);
            #pragma unroll
            for (int i = 0; i < 4; i++) {
                float4 w;
                w.x = s[i][0] + mv.x; w.y = s[i][1] + mv.y;
                w.z = s[i][2] + mv.z; w.w = s[i][3] + mv.w;
                *(float4*)(Ps + (ty * 4 + i) * APAD + tx * 4) = w;
            }
        }
        __syncthreads();

        // Online softmax: 4 threads per row, 16 elements each
        {
            float* pr = Ps + lr * APAD + lc;
            float mx = pr[0];
            #pragma unroll
            for (int u = 1; u < 16; u++) mx = fmaxf(mx, pr[u]);
            mx = fmaxf(mx, __shfl_xor_sync(0xffffffffu, mx, 1));
            mx = fmaxf(mx, __shfl_xor_sync(0xffffffffu, mx, 2));
            const float mold = rm[lr];
            const float mnew = fmaxf(mold, mx);
            float sum = 0.f;
            #pragma unroll
            for (int u = 0; u < 16; u++) {
                const float e = __expf(pr[u] - mnew);
                pr[u] = e;
                sum += e;
            }
            sum += __shfl_xor_sync(0xffffffffu, sum, 1);
            sum += __shfl_xor_sync(0xffffffffu, sum, 2);
            if ((tid & 3) == 0) {
                const float corr = __expf(mold - mnew);
                rm[lr] = mnew;
                rl[lr] = rl[lr] * corr + sum;
                rc[lr] = corr;
            }
        }
        __syncthreads();

        // Rescale accumulators, then O += P @ V
        {
            float corr[4];
            #pragma unroll
            for (int i = 0; i < 4; i++) corr[i] = rc[ty * 4 + i];
            #pragma unroll
            for (int i = 0; i < 4; i++)
                #pragma unroll
                for (int j = 0; j < 4; j++)
                    o[i][j] *= corr[i];

            #pragma unroll
            for (int k = 0; k < 64; k += 4) {
                float4 pv[4], vv[4];
                #pragma unroll
                for (int i = 0; i < 4; i++)
                    pv[i] = *(const float4*)(Ps + (ty * 4 + i) * APAD + k);
                #pragma unroll
                for (int kk = 0; kk < 4; kk++)
                    vv[kk] = *(const float4*)(Vs + (k + kk) * APAD + tx * 4);
                const float* pf = (const float*)pv;
                const float* vf = (const float*)vv;
                #pragma unroll
                for (int kk = 0; kk < 4; kk++)
                    #pragma unroll
                    for (int i = 0; i < 4; i++)
                        #pragma unroll
                        for (int j = 0; j < 4; j++)
                            o[i][j] += pf[i * 4 + kk] * vf[kk * 4 + j];
            }
        }
    }

    // Epilogue: divide by running sum, write O[b, q, h*64 + c]
    {
        float inv[4];
        #pragma unroll
        for (int i = 0; i < 4; i++) inv[i] = 1.f / rl[ty * 4 + i];
        #pragma unroll
        for (int i = 0; i < 4; i++) {
            float4 w;
            w.x = o[i][0] * inv[i]; w.y = o[i][1] * inv[i];
            w.z = o[i][2] * inv[i]; w.w = o[i][3] * inv[i];
            *(float4*)(out + (size_t)(b * SEQ + q0 + ty * 4 + i) * DMODEL
                           + h * 64 + tx * 4) = w;
        }
    }
}

// ---------------------------------------------------------------------------
// kernel_launch
// ---------------------------------------------------------------------------
extern "C" void kernel_launch(void* const* d_in, const int* in_sizes, int n_in,
                              void* d_out, int out_size)
{
    const float* x      = (const float*)d_in[0];
    const float* mask   = (const float*)d_in[1];
    const float* ln1_w  = (const float*)d_in[2];
    const float* ln1_b  = (const float*)d_in[3];
    const float* in_w   = (const float*)d_in[4];
    const float* in_b   = (const float*)d_in[5];
    const float* out_w  = (const float*)d_in[6];
    const float* out_b  = (const float*)d_in[7];
    const float* ln2_w  = (const float*)d_in[8];
    const float* ln2_b  = (const float*)d_in[9];
    const float* ffn1_w = (const float*)d_in[10];
    const float* ffn1_b = (const float*)d_in[11];
    const float* ffn2_w = (const float*)d_in[12];
    const float* ffn2_b = (const float*)d_in[13];
    const float* norm_w = (const float*)d_in[14];
    const float* norm_b = (const float*)d_in[15];

    float *h, *y, *qkv, *att, *ffn;
    cudaGetSymbolAddress((void**)&h,   g_h);
    cudaGetSymbolAddress((void**)&y,   g_y);
    cudaGetSymbolAddress((void**)&qkv, g_qkv);
    cudaGetSymbolAddress((void**)&att, g_att);
    cudaGetSymbolAddress((void**)&ffn, g_ffn);

    cudaFuncSetAttribute(attn_kernel,
                         cudaFuncAttributeMaxDynamicSharedMemorySize,
                         ATT_SMEM_BYTES);

    // h = x
    cudaMemcpyAsync(h, x, sizeof(float) * (size_t)MTOK * DMODEL,
                    cudaMemcpyDeviceToDevice, 0);

    for (int l = 0; l < NLAYER; l++) {
        // y = LN1(h)
        ln_kernel<<<MTOK, 128>>>(h, ln1_w + l * DMODEL, ln1_b + l * DMODEL, y);
        // qkv = y @ in_w + in_b            [4096,512]x[512,1536]
        sgemm128<false, false><<<dim3(12, 32), 256>>>(
            MTOK, 3 * DMODEL, DMODEL,
            y, in_w + (size_t)l * DMODEL * 3 * DMODEL, in_b + l * 3 * DMODEL,
            nullptr, qkv);
        // att = softmax(QK^T * scale + mask) @ V
        attn_kernel<<<dim3(SEQ / 64, NHEAD, BATCH), 256, ATT_SMEM_BYTES>>>(
            qkv, mask, att);
        // h = att @ out_w + out_b + h      [4096,512]x[512,512]
        sgemm128<false, true><<<dim3(4, 32), 256>>>(
            MTOK, DMODEL, DMODEL,
            att, out_w + (size_t)l * DMODEL * DMODEL, out_b + l * DMODEL,
            h, h);
        // y = LN2(h)
        ln_kernel<<<MTOK, 128>>>(h, ln2_w + l * DMODEL, ln2_b + l * DMODEL, y);
        // ffn = relu(y @ ffn1_w + ffn1_b)  [4096,512]x[512,2048]
        sgemm128<true, false><<<dim3(16, 32), 256>>>(
            MTOK, FFDIM, DMODEL,
            y, ffn1_w + (size_t)l * DMODEL * FFDIM, ffn1_b + l * FFDIM,
            nullptr, ffn);
        // h = ffn @ ffn2_w + ffn2_b + h    [4096,2048]x[2048,512]
        sgemm128<false, true><<<dim3(4, 32), 256>>>(
            MTOK, DMODEL, FFDIM,
            ffn, ffn2_w + (size_t)l * FFDIM * DMODEL, ffn2_b + l * DMODEL,
            h, h);
    }

    // out = LN_final(h)
    ln_kernel<<<MTOK, 128>>>(h, norm_w, norm_b, (float*)d_out);
}

// round 12
// speedup vs baseline: 1.0048x; 1.0048x over previous
#include <cuda_runtime.h>

// ---------------------------------------------------------------------------
// TransformerEncoder: B=2, S=2048, D=512, H=8, DH=64, F=2048, L=6, fp32
// Round 11: fma.rn.f32x2 packed-FMA inner loops (GEMM + attention),
//           BM=64 tiles for the N=512 GEMMs (grid 128 -> 256 blocks),
//           register-staged global prefetch in GEMM mainloop.
// ---------------------------------------------------------------------------

#define NLAYER 6
#define DMODEL 512
#define SEQ    2048
#define BATCH  2
#define NHEAD  8
#define DHEAD  64
#define FFDIM  2048
#define MTOK   (BATCH * SEQ)   // 4096 tokens

// Scratch (device globals; allocation is forbidden)
__device__ float g_h  [MTOK * DMODEL];        // residual stream
__device__ float g_y  [MTOK * DMODEL];        // layernorm output
__device__ float g_qkv[MTOK * 3 * DMODEL];    // QKV projection
__device__ float g_att[MTOK * DMODEL];        // attention output
__device__ float g_ffn[MTOK * FFDIM];         // FFN hidden

// ---------------------------------------------------------------------------
// f32x2 packed-math helpers (sm_103a; ptxas never emits these from C++)
// ---------------------------------------------------------------------------
__device__ __forceinline__ unsigned long long bcast2(float x)
{
    unsigned long long r;
    asm("mov.b64 %0, {%1, %1};" : "=l"(r) : "f"(x));
    return r;
}
__device__ __forceinline__ void fma2(unsigned long long& d,
                                     unsigned long long a,
                                     unsigned long long b)
{
    asm("fma.rn.f32x2 %0, %1, %2, %0;" : "+l"(d) : "l"(a), "l"(b));
}
__device__ __forceinline__ void mul2(unsigned long long& d,
                                     unsigned long long a)
{
    asm("mul.rn.f32x2 %0, %0, %1;" : "+l"(d) : "l"(a));
}

// ---------------------------------------------------------------------------
// LayerNorm: one block (128 threads) per token, D=512 (4 floats/thread)
// ---------------------------------------------------------------------------
__global__ void ln_kernel(const float* __restrict__ x,
                          const float* __restrict__ w,
                          const float* __restrict__ b,
                          float* __restrict__ y)
{
    const int token = blockIdx.x;
    const int t = threadIdx.x;
    const float4 v = ((const float4*)(x + (size_t)token * DMODEL))[t];
    float s  = v.x + v.y + v.z + v.w;
    float ss = v.x * v.x + v.y * v.y + v.z * v.z + v.w * v.w;
    #pragma unroll
    for (int o = 16; o > 0; o >>= 1) {
        s  += __shfl_xor_sync(0xffffffffu, s,  o);
        ss += __shfl_xor_sync(0xffffffffu, ss, o);
    }
    __shared__ float rs[4], rss[4];
    const int warp = t >> 5, lane = t & 31;
    if (lane == 0) { rs[warp] = s; rss[warp] = ss; }
    __syncthreads();
    s  = rs[0]  + rs[1]  + rs[2]  + rs[3];
    ss = rss[0] + rss[1] + rss[2] + rss[3];
    const float mean = s * (1.0f / DMODEL);
    const float var  = ss * (1.0f / DMODEL) - mean * mean;
    const float r    = rsqrtf(var + 1e-5f);
    const float4 wv = ((const float4*)w)[t];
    const float4 bv = ((const float4*)b)[t];
    float4 ov;
    ov.x = (v.x - mean) * r * wv.x + bv.x;
    ov.y = (v.y - mean) * r * wv.y + bv.y;
    ov.z = (v.z - mean) * r * wv.z + bv.z;
    ov.w = (v.w - mean) * r * wv.w + bv.w;
    ((float4*)(y + (size_t)token * DMODEL))[t] = ov;
}

// ---------------------------------------------------------------------------
// SGEMM with f32x2 inner loop.
// Tile: BM x 128, BK=8, 256 threads.
//   BM=128 -> 8x8 micro-tile per thread (qkv, ffn1)
//   BM=64  -> 4x8 micro-tile per thread (out-proj, ffn2: doubles grid)
// Accumulators are packed f32x2 pairs over the N dimension.
// ---------------------------------------------------------------------------
template<int BM, bool RELU, bool RES>
__global__ __launch_bounds__(256)
void sgemm_f2(const int M, const int N, const int K,
              const float* __restrict__ A, const float* __restrict__ B,
              const float* __restrict__ bias, const float* __restrict__ res,
              float* __restrict__ C)
{
    constexpr int TM = BM / 16;          // rows per thread: 8 or 4
    __shared__ __align__(16) float As[8][BM];    // transposed A tile
    __shared__ __align__(16) float Bs[8][128];

    const int tid  = threadIdx.x;
    const int row0 = blockIdx.y * BM;
    const int col0 = blockIdx.x * 128;
    const int ty = tid >> 4, tx = tid & 15;

    // loaders
    const int bRow = tid >> 5, bCol = (tid & 31) * 4;
    const float* Bg = B + (size_t)bRow * N + col0 + bCol;
    int aRow, aCol;
    if (BM == 128) { aRow = tid >> 1; aCol = (tid & 1) * 4; }
    else           { aRow = tid >> 2; aCol = (tid & 3) * 2; }
    const float* Ag = A + (size_t)(row0 + aRow) * K + aCol;

    // prefetch first k-tile into registers
    float a_pre[BM == 128 ? 4 : 2];
    if (BM == 128) {
        const float4 t = *(const float4*)Ag;
        a_pre[0] = t.x; a_pre[1] = t.y; a_pre[2] = t.z; a_pre[3] = t.w;
    } else {
        const float2 t = *(const float2*)Ag;
        a_pre[0] = t.x; a_pre[1] = t.y;
    }
    float4 b_pre = *(const float4*)Bg;

    unsigned long long acc[TM][4] = {};   // TM rows x 4 col-pairs

    for (int k0 = 0; k0 < K; k0 += 8) {
        // stage into smem
        if (BM == 128) {
            As[aCol + 0][aRow] = a_pre[0];
            As[aCol + 1][aRow] = a_pre[1];
            As[aCol + 2][aRow] = a_pre[2];
            As[aCol + 3][aRow] = a_pre[3];
        } else {
            As[aCol + 0][aRow] = a_pre[0];
            As[aCol + 1][aRow] = a_pre[1];
        }
        *(float4*)(&Bs[bRow][bCol]) = b_pre;
        __syncthreads();

        // prefetch next k-tile (overlaps with compute below)
        if (k0 + 8 < K) {
            if (BM == 128) {
                const float4 t = *(const float4*)(Ag + k0 + 8);
                a_pre[0] = t.x; a_pre[1] = t.y; a_pre[2] = t.z; a_pre[3] = t.w;
            } else {
                const float2 t = *(const float2*)(Ag + k0 + 8);
                a_pre[0] = t.x; a_pre[1] = t.y;
            }
            b_pre = *(const float4*)(Bg + (size_t)(k0 + 8) * N);
        }

        #pragma unroll
        for (int k = 0; k < 8; k++) {
            // B pairs straight from smem as 64-bit lanes (LDS.128)
            const ulonglong2 rb01 = *(const ulonglong2*)(&Bs[k][tx * 8]);
            const ulonglong2 rb23 = *(const ulonglong2*)(&Bs[k][tx * 8 + 4]);
            float ra[TM];
            if (BM == 128) {
                *(float4*)(ra)     = *(const float4*)(&As[k][ty * 8]);
                *(float4*)(ra + 4) = *(const float4*)(&As[k][ty * 8 + 4]);
            } else {
                *(float4*)(ra)     = *(const float4*)(&As[k][ty * 4]);
            }
            #pragma unroll
            for (int i = 0; i < TM; i++) {
                const unsigned long long av = bcast2(ra[i]);
                fma2(acc[i][0], av, rb01.x);
                fma2(acc[i][1], av, rb01.y);
                fma2(acc[i][2], av, rb23.x);
                fma2(acc[i][3], av, rb23.y);
            }
        }
        __syncthreads();
    }

    // epilogue: unpack pairs, bias/residual/relu, store
    #pragma unroll
    for (int i = 0; i < TM; i++) {
        const size_t r = (size_t)(row0 + ty * TM + i);
        #pragma unroll
        for (int g = 0; g < 2; g++) {
            const int c = col0 + tx * 8 + g * 4;
            const float2 p0 = *(float2*)&acc[i][g * 2 + 0];
            const float2 p1 = *(float2*)&acc[i][g * 2 + 1];
            const float4 bv = *(const float4*)(bias + c);
            float4 v;
            v.x = p0.x + bv.x; v.y = p0.y + bv.y;
            v.z = p1.x + bv.z; v.w = p1.y + bv.w;
            if (RES) {
                const float4 rv = *(const float4*)(res + r * N + c);
                v.x += rv.x; v.y += rv.y; v.z += rv.z; v.w += rv.w;
            }
            if (RELU) {
                v.x = fmaxf(v.x, 0.f); v.y = fmaxf(v.y, 0.f);
                v.z = fmaxf(v.z, 0.f); v.w = fmaxf(v.w, 0.f);
            }
            *(float4*)(C + r * N + c) = v;
        }
    }
}

// ---------------------------------------------------------------------------
// Fused fp32 flash attention with f32x2 inner loops.
// grid (S/64, H, B), 256 threads; 64 queries x full K/V sweep, online softmax.
// Per thread: 4x4 micro-tile (16x16 thread grid); cols packed in f32x2 pairs.
// ---------------------------------------------------------------------------
#define APAD 68
#define ATT_SMEM_BYTES ((4 * 64 * APAD + 3 * 64) * (int)sizeof(float))

__global__ __launch_bounds__(256)
void attn_kernel(const float* __restrict__ qkv,
                 const float* __restrict__ mask,
                 float* __restrict__ out)
{
    extern __shared__ float sm[];
    float* Qs  = sm;                   // [64][APAD]  (scaled Q)
    float* KsT = Qs  + 64 * APAD;      // [d][col]
    float* Vs  = KsT + 64 * APAD;      // [k][col]
    float* Ps  = Vs  + 64 * APAD;      // [row][col]
    float* rm  = Ps  + 64 * APAD;      // running max [64]
    float* rl  = rm  + 64;             // running sum [64]
    float* rc  = rl  + 64;             // correction  [64]

    const int tid = threadIdx.x;
    const int qt = blockIdx.x, h = blockIdx.y, b = blockIdx.z;
    const int q0 = qt * 64;
    const int ty = tid >> 4, tx = tid & 15;
    const int lr = tid >> 2;            // load row   0..63
    const int lc = (tid & 3) * 16;      // load col group

    // Load Q tile, pre-scaled by DH^-0.5 = 0.125
    {
        const float* qsrc = qkv + (size_t)(b * SEQ + q0 + lr) * 1536 + h * 64 + lc;
        float* qdst = Qs + lr * APAD + lc;
        #pragma unroll
        for (int u = 0; u < 16; u += 4) {
            float4 v = *(const float4*)(qsrc + u);
            v.x *= 0.125f; v.y *= 0.125f; v.z *= 0.125f; v.w *= 0.125f;
            *(float4*)(qdst + u) = v;
        }
    }
    if (tid < 64) { rm[tid] = -1e30f; rl[tid] = 0.f; }

    unsigned long long o2[4][2] = {};   // 4 rows x 2 col-pairs

    for (int k0 = 0; k0 < SEQ; k0 += 64) {
        __syncthreads();   // previous PV done; Q/stats visible on first iter
        // Load K (transposed into smem) and V (natural)
        {
            const float* kb = qkv + (size_t)(b * SEQ + k0 + lr) * 1536 + 512 + h * 64 + lc;
            #pragma unroll
            for (int u = 0; u < 16; u += 4) {
                const float4 v = *(const float4*)(kb + u);
                KsT[(lc + u + 0) * APAD + lr] = v.x;
                KsT[(lc + u + 1) * APAD + lr] = v.y;
                KsT[(lc + u + 2) * APAD + lr] = v.z;
                KsT[(lc + u + 3) * APAD + lr] = v.w;
            }
            const float* vb = qkv + (size_t)(b * SEQ + k0 + lr) * 1536 + 1024 + h * 64 + lc;
            float* vd = Vs + lr * APAD + lc;
            #pragma unroll
            for (int u = 0; u < 16; u += 4)
                *(float4*)(vd + u) = *(const float4*)(vb + u);
        }
        __syncthreads();

        // Scores: s[i][j] = sum_d Q[4ty+i][d] * K[4tx+j][d]   (f32x2 over j)
        unsigned long long s2[4][2] = {};
        #pragma unroll
        for (int d = 0; d < 64; d += 4) {
            float qa[4][4];
            #pragma unroll
            for (int i = 0; i < 4; i++)
                *(float4*)qa[i] = *(const float4*)(Qs + (ty * 4 + i) * APAD + d);
            unsigned long long kx[4], ky[4];
            #pragma unroll
            for (int dd = 0; dd < 4; dd++) {
                const ulonglong2 t =
                    *(const ulonglong2*)(KsT + (d + dd) * APAD + tx * 4);
                kx[dd] = t.x; ky[dd] = t.y;
            }
            #pragma unroll
            for (int dd = 0; dd < 4; dd++)
                #pragma unroll
                for (int i = 0; i < 4; i++) {
                    const unsigned long long av = bcast2(qa[i][dd]);
                    fma2(s2[i][0], av, kx[dd]);
                    fma2(s2[i][1], av, ky[dd]);
                }
        }

        // Add mask, write scores to smem
        {
            const float4 mv = *(const float4*)(mask + b * SEQ + k0 + tx * 4);
            #pragma unroll
            for (int i = 0; i < 4; i++) {
                const float2 pa = *(float2*)&s2[i][0];
                const float2 pb = *(float2*)&s2[i][1];
                float4 w;
                w.x = pa.x + mv.x; w.y = pa.y + mv.y;
                w.z = pb.x + mv.z; w.w = pb.y + mv.w;
                *(float4*)(Ps + (ty * 4 + i) * APAD + tx * 4) = w;
            }
        }
        __syncthreads();

        // Online softmax: 4 threads per row, 16 elements each
        {
            float* pr = Ps + lr * APAD + lc;
            float mx = pr[0];
            #pragma unroll
            for (int u = 1; u < 16; u++) mx = fmaxf(mx, pr[u]);
            mx = fmaxf(mx, __shfl_xor_sync(0xffffffffu, mx, 1));
            mx = fmaxf(mx, __shfl_xor_sync(0xffffffffu, mx, 2));
            const float mold = rm[lr];
            const float mnew = fmaxf(mold, mx);
            float sum = 0.f;
            #pragma unroll
            for (int u = 0; u < 16; u++) {
                const float e = __expf(pr[u] - mnew);
                pr[u] = e;
                sum += e;
            }
            sum += __shfl_xor_sync(0xffffffffu, sum, 1);
            sum += __shfl_xor_sync(0xffffffffu, sum, 2);
            if ((tid & 3) == 0) {
                const float corr = __expf(mold - mnew);
                rm[lr] = mnew;
                rl[lr] = rl[lr] * corr + sum;
                rc[lr] = corr;
            }
        }
        __syncthreads();

        // Rescale accumulators, then O += P @ V   (f32x2 over cols)
        {
            #pragma unroll
            for (int i = 0; i < 4; i++) {
                const unsigned long long cv = bcast2(rc[ty * 4 + i]);
                mul2(o2[i][0], cv);
                mul2(o2[i][1], cv);
            }
            #pragma unroll
            for (int k = 0; k < 64; k += 4) {
                float pa[4][4];
                #pragma unroll
                for (int i = 0; i < 4; i++)
                    *(float4*)pa[i] = *(const float4*)(Ps + (ty * 4 + i) * APAD + k);
                unsigned long long vx[4], vy[4];
                #pragma unroll
                for (int kk = 0; kk < 4; kk++) {
                    const ulonglong2 t =
                        *(const ulonglong2*)(Vs + (k + kk) * APAD + tx * 4);
                    vx[kk] = t.x; vy[kk] = t.y;
                }
                #pragma unroll
                for (int kk = 0; kk < 4; kk++)
                    #pragma unroll
                    for (int i = 0; i < 4; i++) {
                        const unsigned long long av = bcast2(pa[i][kk]);
                        fma2(o2[i][0], av, vx[kk]);
                        fma2(o2[i][1], av, vy[kk]);
                    }
            }
        }
    }

    // Epilogue: divide by running sum, write O[b, q, h*64 + c]
    {
        #pragma unroll
        for (int i = 0; i < 4; i++) {
            const float inv = 1.f / rl[ty * 4 + i];
            const float2 p0 = *(float2*)&o2[i][0];
            const float2 p1 = *(float2*)&o2[i][1];
            float4 w;
            w.x = p0.x * inv; w.y = p0.y * inv;
            w.z = p1.x * inv; w.w = p1.y * inv;
            *(float4*)(out + (size_t)(b * SEQ + q0 + ty * 4 + i) * DMODEL
                           + h * 64 + tx * 4) = w;
        }
    }
}

// ---------------------------------------------------------------------------
// kernel_launch
// ---------------------------------------------------------------------------
extern "C" void kernel_launch(void* const* d_in, const int* in_sizes, int n_in,
                              void* d_out, int out_size)
{
    const float* x      = (const float*)d_in[0];
    const float* mask   = (const float*)d_in[1];
    const float* ln1_w  = (const float*)d_in[2];
    const float* ln1_b  = (const float*)d_in[3];
    const float* in_w   = (const float*)d_in[4];
    const float* in_b   = (const float*)d_in[5];
    const float* out_w  = (const float*)d_in[6];
    const float* out_b  = (const float*)d_in[7];
    const float* ln2_w  = (const float*)d_in[8];
    const float* ln2_b  = (const float*)d_in[9];
    const float* ffn1_w = (const float*)d_in[10];
    const float* ffn1_b = (const float*)d_in[11];
    const float* ffn2_w = (const float*)d_in[12];
    const float* ffn2_b = (const float*)d_in[13];
    const float* norm_w = (const float*)d_in[14];
    const float* norm_b = (const float*)d_in[15];

    float *h, *y, *qkv, *att, *ffn;
    cudaGetSymbolAddress((void**)&h,   g_h);
    cudaGetSymbolAddress((void**)&y,   g_y);
    cudaGetSymbolAddress((void**)&qkv, g_qkv);
    cudaGetSymbolAddress((void**)&att, g_att);
    cudaGetSymbolAddress((void**)&ffn, g_ffn);

    cudaFuncSetAttribute(attn_kernel,
                         cudaFuncAttributeMaxDynamicSharedMemorySize,
                         ATT_SMEM_BYTES);

    // h = x
    cudaMemcpyAsync(h, x, sizeof(float) * (size_t)MTOK * DMODEL,
                    cudaMemcpyDeviceToDevice, 0);

    for (int l = 0; l < NLAYER; l++) {
        // y = LN1(h)
        ln_kernel<<<MTOK, 128>>>(h, ln1_w + l * DMODEL, ln1_b + l * DMODEL, y);
        // qkv = y @ in_w + in_b            [4096,512]x[512,1536]
        sgemm_f2<128, false, false><<<dim3(12, 32), 256>>>(
            MTOK, 3 * DMODEL, DMODEL,
            y, in_w + (size_t)l * DMODEL * 3 * DMODEL, in_b + l * 3 * DMODEL,
            nullptr, qkv);
        // att = softmax(QK^T * scale + mask) @ V
        attn_kernel<<<dim3(SEQ / 64, NHEAD, BATCH), 256, ATT_SMEM_BYTES>>>(
            qkv, mask, att);
        // h = att @ out_w + out_b + h      [4096,512]x[512,512]  (BM=64: 256 blocks)
        sgemm_f2<64, false, true><<<dim3(4, 64), 256>>>(
            MTOK, DMODEL, DMODEL,
            att, out_w + (size_t)l * DMODEL * DMODEL, out_b + l * DMODEL,
            h, h);
        // y = LN2(h)
        ln_kernel<<<MTOK, 128>>>(h, ln2_w + l * DMODEL, ln2_b + l * DMODEL, y);
        // ffn = relu(y @ ffn1_w + ffn1_b)  [4096,512]x[512,2048]
        sgemm_f2<128, true, false><<<dim3(16, 32), 256>>>(
            MTOK, FFDIM, DMODEL,
            y, ffn1_w + (size_t)l * DMODEL * FFDIM, ffn1_b + l * FFDIM,
            nullptr, ffn);
        // h = ffn @ ffn2_w + ffn2_b + h    [4096,2048]x[2048,512]  (BM=64)
        sgemm_f2<64, false, true><<<dim3(4, 64), 256>>>(
            MTOK, DMODEL, FFDIM,
            ffn, ffn2_w + (size_t)l * FFDIM * DMODEL, ffn2_b + l * DMODEL,
            h, h);
    }

    // out = LN_final(h)
    ln_kernel<<<MTOK, 128>>>(h, norm_w, norm_b, (float*)d_out);
}

// round 13
// speedup vs baseline: 1.0053x; 1.0005x over previous
#include <cuda_runtime.h>

// ---------------------------------------------------------------------------
// TransformerEncoder: B=2, S=2048, D=512, H=8, DH=64, F=2048, L=6, fp32
// Round 11: fma.rn.f32x2 packed-FMA inner loops (GEMM + attention),
//           BM=64 tiles for the N=512 GEMMs (grid 128 -> 256 blocks),
//           register-staged global prefetch in GEMM mainloop.
// ---------------------------------------------------------------------------

#define NLAYER 6
#define DMODEL 512
#define SEQ    2048
#define BATCH  2
#define NHEAD  8
#define DHEAD  64
#define FFDIM  2048
#define MTOK   (BATCH * SEQ)   // 4096 tokens

// Scratch (device globals; allocation is forbidden)
__device__ float g_h  [MTOK * DMODEL];        // residual stream
__device__ float g_y  [MTOK * DMODEL];        // layernorm output
__device__ float g_qkv[MTOK * 3 * DMODEL];    // QKV projection
__device__ float g_att[MTOK * DMODEL];        // attention output
__device__ float g_ffn[MTOK * FFDIM];         // FFN hidden

// ---------------------------------------------------------------------------
// f32x2 packed-math helpers (sm_103a; ptxas never emits these from C++)
// ---------------------------------------------------------------------------
__device__ __forceinline__ unsigned long long bcast2(float x)
{
    unsigned long long r;
    asm("mov.b64 %0, {%1, %1};" : "=l"(r) : "f"(x));
    return r;
}
__device__ __forceinline__ void fma2(unsigned long long& d,
                                     unsigned long long a,
                                     unsigned long long b)
{
    asm("fma.rn.f32x2 %0, %1, %2, %0;" : "+l"(d) : "l"(a), "l"(b));
}
__device__ __forceinline__ void mul2(unsigned long long& d,
                                     unsigned long long a)
{
    asm("mul.rn.f32x2 %0, %0, %1;" : "+l"(d) : "l"(a));
}

// ---------------------------------------------------------------------------
// LayerNorm: one block (128 threads) per token, D=512 (4 floats/thread)
// ---------------------------------------------------------------------------
__global__ void ln_kernel(const float* __restrict__ x,
                          const float* __restrict__ w,
                          const float* __restrict__ b,
                          float* __restrict__ y)
{
    const int token = blockIdx.x;
    const int t = threadIdx.x;
    const float4 v = ((const float4*)(x + (size_t)token * DMODEL))[t];
    float s  = v.x + v.y + v.z + v.w;
    float ss = v.x * v.x + v.y * v.y + v.z * v.z + v.w * v.w;
    #pragma unroll
    for (int o = 16; o > 0; o >>= 1) {
        s  += __shfl_xor_sync(0xffffffffu, s,  o);
        ss += __shfl_xor_sync(0xffffffffu, ss, o);
    }
    __shared__ float rs[4], rss[4];
    const int warp = t >> 5, lane = t & 31;
    if (lane == 0) { rs[warp] = s; rss[warp] = ss; }
    __syncthreads();
    s  = rs[0]  + rs[1]  + rs[2]  + rs[3];
    ss = rss[0] + rss[1] + rss[2] + rss[3];
    const float mean = s * (1.0f / DMODEL);
    const float var  = ss * (1.0f / DMODEL) - mean * mean;
    const float r    = rsqrtf(var + 1e-5f);
    const float4 wv = ((const float4*)w)[t];
    const float4 bv = ((const float4*)b)[t];
    float4 ov;
    ov.x = (v.x - mean) * r * wv.x + bv.x;
    ov.y = (v.y - mean) * r * wv.y + bv.y;
    ov.z = (v.z - mean) * r * wv.z + bv.z;
    ov.w = (v.w - mean) * r * wv.w + bv.w;
    ((float4*)(y + (size_t)token * DMODEL))[t] = ov;
}

// ---------------------------------------------------------------------------
// SGEMM with f32x2 inner loop.
// Tile: BM x 128, BK=8, 256 threads.
//   BM=128 -> 8x8 micro-tile per thread (qkv, ffn1)
//   BM=64  -> 4x8 micro-tile per thread (out-proj, ffn2: doubles grid)
// Accumulators are packed f32x2 pairs over the N dimension.
// ---------------------------------------------------------------------------
template<int BM, bool RELU, bool RES>
__global__ __launch_bounds__(256)
void sgemm_f2(const int M, const int N, const int K,
              const float* __restrict__ A, const float* __restrict__ B,
              const float* __restrict__ bias, const float* __restrict__ res,
              float* __restrict__ C)
{
    constexpr int TM = BM / 16;          // rows per thread: 8 or 4
    __shared__ __align__(16) float As[8][BM];    // transposed A tile
    __shared__ __align__(16) float Bs[8][128];

    const int tid  = threadIdx.x;
    const int row0 = blockIdx.y * BM;
    const int col0 = blockIdx.x * 128;
    const int ty = tid >> 4, tx = tid & 15;

    // loaders
    const int bRow = tid >> 5, bCol = (tid & 31) * 4;
    const float* Bg = B + (size_t)bRow * N + col0 + bCol;
    int aRow, aCol;
    if (BM == 128) { aRow = tid >> 1; aCol = (tid & 1) * 4; }
    else           { aRow = tid >> 2; aCol = (tid & 3) * 2; }
    const float* Ag = A + (size_t)(row0 + aRow) * K + aCol;

    // prefetch first k-tile into registers
    float a_pre[BM == 128 ? 4 : 2];
    if (BM == 128) {
        const float4 t = *(const float4*)Ag;
        a_pre[0] = t.x; a_pre[1] = t.y; a_pre[2] = t.z; a_pre[3] = t.w;
    } else {
        const float2 t = *(const float2*)Ag;
        a_pre[0] = t.x; a_pre[1] = t.y;
    }
    float4 b_pre = *(const float4*)Bg;

    unsigned long long acc[TM][4] = {};   // TM rows x 4 col-pairs

    for (int k0 = 0; k0 < K; k0 += 8) {
        // stage into smem
        if (BM == 128) {
            As[aCol + 0][aRow] = a_pre[0];
            As[aCol + 1][aRow] = a_pre[1];
            As[aCol + 2][aRow] = a_pre[2];
            As[aCol + 3][aRow] = a_pre[3];
        } else {
            As[aCol + 0][aRow] = a_pre[0];
            As[aCol + 1][aRow] = a_pre[1];
        }
        *(float4*)(&Bs[bRow][bCol]) = b_pre;
        __syncthreads();

        // prefetch next k-tile (overlaps with compute below)
        if (k0 + 8 < K) {
            if (BM == 128) {
                const float4 t = *(const float4*)(Ag + k0 + 8);
                a_pre[0] = t.x; a_pre[1] = t.y; a_pre[2] = t.z; a_pre[3] = t.w;
            } else {
                const float2 t = *(const float2*)(Ag + k0 + 8);
                a_pre[0] = t.x; a_pre[1] = t.y;
            }
            b_pre = *(const float4*)(Bg + (size_t)(k0 + 8) * N);
        }

        #pragma unroll
        for (int k = 0; k < 8; k++) {
            // B pairs straight from smem as 64-bit lanes (LDS.128)
            const ulonglong2 rb01 = *(const ulonglong2*)(&Bs[k][tx * 8]);
            const ulonglong2 rb23 = *(const ulonglong2*)(&Bs[k][tx * 8 + 4]);
            float ra[TM];
            if (BM == 128) {
                *(float4*)(ra)     = *(const float4*)(&As[k][ty * 8]);
                *(float4*)(ra + 4) = *(const float4*)(&As[k][ty * 8 + 4]);
            } else {
                *(float4*)(ra)     = *(const float4*)(&As[k][ty * 4]);
            }
            #pragma unroll
            for (int i = 0; i < TM; i++) {
                const unsigned long long av = bcast2(ra[i]);
                fma2(acc[i][0], av, rb01.x);
                fma2(acc[i][1], av, rb01.y);
                fma2(acc[i][2], av, rb23.x);
                fma2(acc[i][3], av, rb23.y);
            }
        }
        __syncthreads();
    }

    // epilogue: unpack pairs, bias/residual/relu, store
    #pragma unroll
    for (int i = 0; i < TM; i++) {
        const size_t r = (size_t)(row0 + ty * TM + i);
        #pragma unroll
        for (int g = 0; g < 2; g++) {
            const int c = col0 + tx * 8 + g * 4;
            const float2 p0 = *(float2*)&acc[i][g * 2 + 0];
            const float2 p1 = *(float2*)&acc[i][g * 2 + 1];
            const float4 bv = *(const float4*)(bias + c);
            float4 v;
            v.x = p0.x + bv.x; v.y = p0.y + bv.y;
            v.z = p1.x + bv.z; v.w = p1.y + bv.w;
            if (RES) {
                const float4 rv = *(const float4*)(res + r * N + c);
                v.x += rv.x; v.y += rv.y; v.z += rv.z; v.w += rv.w;
            }
            if (RELU) {
                v.x = fmaxf(v.x, 0.f); v.y = fmaxf(v.y, 0.f);
                v.z = fmaxf(v.z, 0.f); v.w = fmaxf(v.w, 0.f);
            }
            *(float4*)(C + r * N + c) = v;
        }
    }
}

// ---------------------------------------------------------------------------
// Fused fp32 flash attention with f32x2 inner loops.
// grid (S/64, H, B), 256 threads; 64 queries x full K/V sweep, online softmax.
// Per thread: 4x4 micro-tile (16x16 thread grid); cols packed in f32x2 pairs.
// ---------------------------------------------------------------------------
#define APAD 68
#define ATT_SMEM_BYTES ((4 * 64 * APAD + 3 * 64) * (int)sizeof(float))

__global__ __launch_bounds__(256)
void attn_kernel(const float* __restrict__ qkv,
                 const float* __restrict__ mask,
                 float* __restrict__ out)
{
    extern __shared__ float sm[];
    float* Qs  = sm;                   // [64][APAD]  (scaled Q)
    float* KsT = Qs  + 64 * APAD;      // [d][col]
    float* Vs  = KsT + 64 * APAD;      // [k][col]
    float* Ps  = Vs  + 64 * APAD;      // [row][col]
    float* rm  = Ps  + 64 * APAD;      // running max [64]
    float* rl  = rm  + 64;             // running sum [64]
    float* rc  = rl  + 64;             // correction  [64]

    const int tid = threadIdx.x;
    const int qt = blockIdx.x, h = blockIdx.y, b = blockIdx.z;
    const int q0 = qt * 64;
    const int ty = tid >> 4, tx = tid & 15;
    const int lr = tid >> 2;            // load row   0..63
    const int lc = (tid & 3) * 16;      // load col group

    // Load Q tile, pre-scaled by DH^-0.5 = 0.125
    {
        const float* qsrc = qkv + (size_t)(b * SEQ + q0 + lr) * 1536 + h * 64 + lc;
        float* qdst = Qs + lr * APAD + lc;
        #pragma unroll
        for (int u = 0; u < 16; u += 4) {
            float4 v = *(const float4*)(qsrc + u);
            v.x *= 0.125f; v.y *= 0.125f; v.z *= 0.125f; v.w *= 0.125f;
            *(float4*)(qdst + u) = v;
        }
    }
    if (tid < 64) { rm[tid] = -1e30f; rl[tid] = 0.f; }

    unsigned long long o2[4][2] = {};   // 4 rows x 2 col-pairs

    for (int k0 = 0; k0 < SEQ; k0 += 64) {
        __syncthreads();   // previous PV done; Q/stats visible on first iter
        // Load K (transposed into smem) and V (natural)
        {
            const float* kb = qkv + (size_t)(b * SEQ + k0 + lr) * 1536 + 512 + h * 64 + lc;
            #pragma unroll
            for (int u = 0; u < 16; u += 4) {
                const float4 v = *(const float4*)(kb + u);
                KsT[(lc + u + 0) * APAD + lr] = v.x;
                KsT[(lc + u + 1) * APAD + lr] = v.y;
                KsT[(lc + u + 2) * APAD + lr] = v.z;
                KsT[(lc + u + 3) * APAD + lr] = v.w;
            }
            const float* vb = qkv + (size_t)(b * SEQ + k0 + lr) * 1536 + 1024 + h * 64 + lc;
            float* vd = Vs + lr * APAD + lc;
            #pragma unroll
            for (int u = 0; u < 16; u += 4)
                *(float4*)(vd + u) = *(const float4*)(vb + u);
        }
        __syncthreads();

        // Scores: s[i][j] = sum_d Q[4ty+i][d] * K[4tx+j][d]   (f32x2 over j)
        unsigned long long s2[4][2] = {};
        #pragma unroll
        for (int d = 0; d < 64; d += 4) {
            float qa[4][4];
            #pragma unroll
            for (int i = 0; i < 4; i++)
                *(float4*)qa[i] = *(const float4*)(Qs + (ty * 4 + i) * APAD + d);
            unsigned long long kx[4], ky[4];
            #pragma unroll
            for (int dd = 0; dd < 4; dd++) {
                const ulonglong2 t =
                    *(const ulonglong2*)(KsT + (d + dd) * APAD + tx * 4);
                kx[dd] = t.x; ky[dd] = t.y;
            }
            #pragma unroll
            for (int dd = 0; dd < 4; dd++)
                #pragma unroll
                for (int i = 0; i < 4; i++) {
                    const unsigned long long av = bcast2(qa[i][dd]);
                    fma2(s2[i][0], av, kx[dd]);
                    fma2(s2[i][1], av, ky[dd]);
                }
        }

        // Add mask, write scores to smem
        {
            const float4 mv = *(const float4*)(mask + b * SEQ + k0 + tx * 4);
            #pragma unroll
            for (int i = 0; i < 4; i++) {
                const float2 pa = *(float2*)&s2[i][0];
                const float2 pb = *(float2*)&s2[i][1];
                float4 w;
                w.x = pa.x + mv.x; w.y = pa.y + mv.y;
                w.z = pb.x + mv.z; w.w = pb.y + mv.w;
                *(float4*)(Ps + (ty * 4 + i) * APAD + tx * 4) = w;
            }
        }
        __syncthreads();

        // Online softmax: 4 threads per row, 16 elements each
        {
            float* pr = Ps + lr * APAD + lc;
            float mx = pr[0];
            #pragma unroll
            for (int u = 1; u < 16; u++) mx = fmaxf(mx, pr[u]);
            mx = fmaxf(mx, __shfl_xor_sync(0xffffffffu, mx, 1));
            mx = fmaxf(mx, __shfl_xor_sync(0xffffffffu, mx, 2));
            const float mold = rm[lr];
            const float mnew = fmaxf(mold, mx);
            float sum = 0.f;
            #pragma unroll
            for (int u = 0; u < 16; u++) {
                const float e = __expf(pr[u] - mnew);
                pr[u] = e;
                sum += e;
            }
            sum += __shfl_xor_sync(0xffffffffu, sum, 1);
            sum += __shfl_xor_sync(0xffffffffu, sum, 2);
            if ((tid & 3) == 0) {
                const float corr = __expf(mold - mnew);
                rm[lr] = mnew;
                rl[lr] = rl[lr] * corr + sum;
                rc[lr] = corr;
            }
        }
        __syncthreads();

        // Rescale accumulators, then O += P @ V   (f32x2 over cols)
        {
            #pragma unroll
            for (int i = 0; i < 4; i++) {
                const unsigned long long cv = bcast2(rc[ty * 4 + i]);
                mul2(o2[i][0], cv);
                mul2(o2[i][1], cv);
            }
            #pragma unroll
            for (int k = 0; k < 64; k += 4) {
                float pa[4][4];
                #pragma unroll
                for (int i = 0; i < 4; i++)
                    *(float4*)pa[i] = *(const float4*)(Ps + (ty * 4 + i) * APAD + k);
                unsigned long long vx[4], vy[4];
                #pragma unroll
                for (int kk = 0; kk < 4; kk++) {
                    const ulonglong2 t =
                        *(const ulonglong2*)(Vs + (k + kk) * APAD + tx * 4);
                    vx[kk] = t.x; vy[kk] = t.y;
                }
                #pragma unroll
                for (int kk = 0; kk < 4; kk++)
                    #pragma unroll
                    for (int i = 0; i < 4; i++) {
                        const unsigned long long av = bcast2(pa[i][kk]);
                        fma2(o2[i][0], av, vx[kk]);
                        fma2(o2[i][1], av, vy[kk]);
                    }
            }
        }
    }

    // Epilogue: divide by running sum, write O[b, q, h*64 + c]
    {
        #pragma unroll
        for (int i = 0; i < 4; i++) {
            const float inv = 1.f / rl[ty * 4 + i];
            const float2 p0 = *(float2*)&o2[i][0];
            const float2 p1 = *(float2*)&o2[i][1];
            float4 w;
            w.x = p0.x * inv; w.y = p0.y * inv;
            w.z = p1.x * inv; w.w = p1.y * inv;
            *(float4*)(out + (size_t)(b * SEQ + q0 + ty * 4 + i) * DMODEL
                           + h * 64 + tx * 4) = w;
        }
    }
}

// ---------------------------------------------------------------------------
// kernel_launch
// ---------------------------------------------------------------------------
extern "C" void kernel_launch(void* const* d_in, const int* in_sizes, int n_in,
                              void* d_out, int out_size)
{
    const float* x      = (const float*)d_in[0];
    const float* mask   = (const float*)d_in[1];
    const float* ln1_w  = (const float*)d_in[2];
    const float* ln1_b  = (const float*)d_in[3];
    const float* in_w   = (const float*)d_in[4];
    const float* in_b   = (const float*)d_in[5];
    const float* out_w  = (const float*)d_in[6];
    const float* out_b  = (const float*)d_in[7];
    const float* ln2_w  = (const float*)d_in[8];
    const float* ln2_b  = (const float*)d_in[9];
    const float* ffn1_w = (const float*)d_in[10];
    const float* ffn1_b = (const float*)d_in[11];
    const float* ffn2_w = (const float*)d_in[12];
    const float* ffn2_b = (const float*)d_in[13];
    const float* norm_w = (const float*)d_in[14];
    const float* norm_b = (const float*)d_in[15];

    float *h, *y, *qkv, *att, *ffn;
    cudaGetSymbolAddress((void**)&h,   g_h);
    cudaGetSymbolAddress((void**)&y,   g_y);
    cudaGetSymbolAddress((void**)&qkv, g_qkv);
    cudaGetSymbolAddress((void**)&att, g_att);
    cudaGetSymbolAddress((void**)&ffn, g_ffn);

    cudaFuncSetAttribute(attn_kernel,
                         cudaFuncAttributeMaxDynamicSharedMemorySize,
                         ATT_SMEM_BYTES);

    // h = x
    cudaMemcpyAsync(h, x, sizeof(float) * (size_t)MTOK * DMODEL,
                    cudaMemcpyDeviceToDevice, 0);

    for (int l = 0; l < NLAYER; l++) {
        // y = LN1(h)
        ln_kernel<<<MTOK, 128>>>(h, ln1_w + l * DMODEL, ln1_b + l * DMODEL, y);
        // qkv = y @ in_w + in_b            [4096,512]x[512,1536]
        sgemm_f2<128, false, false><<<dim3(12, 32), 256>>>(
            MTOK, 3 * DMODEL, DMODEL,
            y, in_w + (size_t)l * DMODEL * 3 * DMODEL, in_b + l * 3 * DMODEL,
            nullptr, qkv);
        // att = softmax(QK^T * scale + mask) @ V
        attn_kernel<<<dim3(SEQ / 64, NHEAD, BATCH), 256, ATT_SMEM_BYTES>>>(
            qkv, mask, att);
        // h = att @ out_w + out_b + h      [4096,512]x[512,512]  (BM=64: 256 blocks)
        sgemm_f2<64, false, true><<<dim3(4, 64), 256>>>(
            MTOK, DMODEL, DMODEL,
            att, out_w + (size_t)l * DMODEL * DMODEL, out_b + l * DMODEL,
            h, h);
        // y = LN2(h)
        ln_kernel<<<MTOK, 128>>>(h, ln2_w + l * DMODEL, ln2_b + l * DMODEL, y);
        // ffn = relu(y @ ffn1_w + ffn1_b)  [4096,512]x[512,2048]
        sgemm_f2<128, true, false><<<dim3(16, 32), 256>>>(
            MTOK, FFDIM, DMODEL,
            y, ffn1_w + (size_t)l * DMODEL * FFDIM, ffn1_b + l * FFDIM,
            nullptr, ffn);
        // h = ffn @ ffn2_w + ffn2_b + h    [4096,2048]x[2048,512]  (BM=64)
        sgemm_f2<64, false, true><<<dim3(4, 64), 256>>>(
            MTOK, DMODEL, FFDIM,
            ffn, ffn2_w + (size_t)l * FFDIM * DMODEL, ffn2_b + l * DMODEL,
            h, h);
    }

    // out = LN_final(h)
    ln_kernel<<<MTOK, 128>>>(h, norm_w, norm_b, (float*)d_out);
}